// round 5
// baseline (speedup 1.0000x reference)
#include <cuda_runtime.h>
#include <cuda_bf16.h>

// CasamentoMult on GB300 — MUFU/FMA pipe-balanced hybrid.
// sigma = 1/sqrt(2*pi) => log_sqrt_pi == 0; pair term = exp(-pi*diff^2)
//   = 2^(-(SC*diff)^2), SC = sqrt(pi*log2(e)).  Collapsed form:
//  total = NE + sum_k [ 0.5*(gy+gd - c1 - c2) - s ]
//             + 0.5*e(d[0]-y[0]) - 0.5*e(d[NE]-y[NE]),   NE = N-2,
//  gy=e(y1-y0) gd=e(d1-d0) c1=e(d1-y0) c2=e(d0-y1) s=e(d0-y0).
// gy,gd,s,c1 -> MUFU ex2; c2 -> packed f32x2 polynomial (per element pair).

#define NBLK 444           // 148 SMs * 3 resident blocks -> one full wave
#define NTHR 256

__device__ float    g_partials[NBLK];
__device__ unsigned g_ticket = 0;

#define SC     2.1289340388624523f   // sqrt(pi * log2(e))
#define MAGICF 12582912.0f           // 1.5 * 2^23  (bits 0x4B400000, low 9 bits = 0)
#define RMIN   0x4B3FFF82            // as_int(MAGICF) - 126  (exponent clamp)

// ---- f32x2 packed helpers (containers are doubles; FP64 pipe never used) ----
__device__ __forceinline__ double pk2(float lo, float hi) {
    double r; asm("mov.b64 %0, {%1, %2};" : "=d"(r) : "f"(lo), "f"(hi)); return r;
}
__device__ __forceinline__ float lo2(double v) {
    return __uint_as_float((unsigned)__double2loint(v));
}
__device__ __forceinline__ float hi2(double v) {
    return __uint_as_float((unsigned)__double2hiint(v));
}
__device__ __forceinline__ double fma2(double a, double b, double c) {
    double r; asm("fma.rn.f32x2 %0, %1, %2, %3;" : "=d"(r) : "d"(a), "d"(b), "d"(c)); return r;
}
__device__ __forceinline__ double mul2(double a, double b) {
    double r; asm("mul.rn.f32x2 %0, %1, %2;" : "=d"(r) : "d"(a), "d"(b)); return r;
}

__device__ __forceinline__ float ex2f(float a) {   // 2^a
    float r; asm("ex2.approx.f32 %0, %1;" : "=f"(r) : "f"(a)); return r;
}
__device__ __forceinline__ float gex_raw(float x) {  // exp(-pi*x^2), scalar
    float u = x * SC;
    return ex2f(-u * u);
}

__global__ void __launch_bounds__(NTHR, 3)
casa_fused(const float* __restrict__ d, const float* __restrict__ y,
           int NE, int ngroups, float* __restrict__ out) {
    // packed constants (built once per thread)
    const double NEG1 = pk2(-1.f, -1.f);
    const double SC2  = pk2(SC, SC);
    const double MG2  = pk2(MAGICF, MAGICF);
    const double K4   = pk2(0.0096181291f, 0.0096181291f);
    const double K3   = pk2(0.0555041087f, 0.0555041087f);
    const double K2   = pk2(0.2402265069f, 0.2402265069f);
    const double K1   = pk2(0.6931471806f, 0.6931471806f);
    const double K0   = pk2(1.0f, 1.0f);

    float accP0 = 0.f, accP1 = 0.f;   // gy+gd
    float accC1 = 0.f;                // c1 (MUFU)
    float accS0 = 0.f, accS1 = 0.f;   // s
    float accCa = 0.f, accCb = 0.f;   // c2 (poly halves)
    const int stride = gridDim.x * blockDim.x;

    for (int g = blockIdx.x * blockDim.x + threadIdx.x; g < ngroups; g += stride) {
        const int base = g << 3;                   // 8 elements per group
        const float4 dA = *reinterpret_cast<const float4*>(d + base);
        const float4 dB = *reinterpret_cast<const float4*>(d + base + 4);
        const float4 yA = *reinterpret_cast<const float4*>(y + base);
        const float4 yB = *reinterpret_cast<const float4*>(y + base + 4);
        const float d8r = __ldg(d + base + 8);
        const float y8r = __ldg(y + base + 8);

        // prescaled (y, d) packs, 9 values
        double YD[9];
        YD[0] = mul2(pk2(yA.x, dA.x), SC2);
        YD[1] = mul2(pk2(yA.y, dA.y), SC2);
        YD[2] = mul2(pk2(yA.z, dA.z), SC2);
        YD[3] = mul2(pk2(yA.w, dA.w), SC2);
        YD[4] = mul2(pk2(yB.x, dB.x), SC2);
        YD[5] = mul2(pk2(yB.y, dB.y), SC2);
        YD[6] = mul2(pk2(yB.z, dB.z), SC2);
        YD[7] = mul2(pk2(yB.w, dB.w), SC2);
        YD[8] = mul2(pk2(y8r,  d8r ), SC2);

        #pragma unroll
        for (int i = 0; i < 8; i += 2) {
            // ---- element i and i+1, MUFU part ----
            #pragma unroll
            for (int e = 0; e < 2; e++) {
                const int j = i + e;
                // (gy, gd): packed diff of (Y,D) pairs
                double u2 = fma2(YD[j], NEG1, YD[j + 1]);
                double q  = mul2(u2, u2);
                double nq = mul2(q, NEG1);
                float gy = ex2f(lo2(nq));
                float gd = ex2f(hi2(nq));
                // (s, c1): (D_j - Y_j, D_{j+1} - Y_j)
                double Dp = pk2(hi2(YD[j]), hi2(YD[j + 1]));
                double Yp = pk2(lo2(YD[j]), lo2(YD[j]));
                double us = fma2(Yp, NEG1, Dp);
                double qs = mul2(us, us);
                double ns = mul2(qs, NEG1);
                float s  = ex2f(lo2(ns));
                float c1 = ex2f(hi2(ns));
                if (e == 0) { accP0 += gy + gd; accS0 += s; }
                else        { accP1 += gy + gd; accS1 += s; }
                accC1 += c1;
            }
            // ---- c2 pair via packed polynomial: (D_i - Y_{i+1}, D_{i+1} - Y_{i+2}) ----
            double Dp2 = pk2(hi2(YD[i]), hi2(YD[i + 1]));
            double Yp2 = pk2(lo2(YD[i + 1]), lo2(YD[i + 2]));
            double u  = fma2(Yp2, NEG1, Dp2);
            double v  = mul2(u, u);                 // v >= 0; 2^(-v) wanted
            double r  = fma2(v, NEG1, MG2);         // MAGIC - v  (round via magic)
            double rv = fma2(r, NEG1, MG2);         // round(v)
            double f  = fma2(v, NEG1, rv);          // frac = round(v) - v  in [-.5,.5]
            double p  = fma2(f, K4, K3);
            p = fma2(p, f, K2);
            p = fma2(p, f, K1);
            p = fma2(p, f, K0);                     // 2^frac
            int r0 = __double2loint(r), r1 = __double2hiint(r);
            int p0 = __double2loint(p), p1 = __double2hiint(p);
            r0 = max(r0, (int)RMIN);                // clamp exponent (v > 126 -> ~0)
            r1 = max(r1, (int)RMIN);
            // bits(2^frac) + (-round(v))<<23 ; as_int(MAGICF)<<23 == 0 mod 2^32
            unsigned b0 = (unsigned)r0 * 8388608u + (unsigned)p0;
            unsigned b1 = (unsigned)r1 * 8388608u + (unsigned)p1;
            accCa += __uint_as_float(b0);
            accCb += __uint_as_float(b1);
        }
    }

    // total = 0.5*(P - C1 - C2) - S
    float acc = fmaf(((accP0 + accP1) - accC1) - (accCa + accCb), 0.5f,
                     -(accS0 + accS1));

    // block reduce (float)
    #pragma unroll
    for (int o = 16; o; o >>= 1) acc += __shfl_down_sync(0xffffffffu, acc, o);

    __shared__ float sh[NTHR / 32];
    __shared__ bool  s_last;
    const int lane = threadIdx.x & 31;
    const int w    = threadIdx.x >> 5;
    if (lane == 0) sh[w] = acc;
    __syncthreads();
    if (threadIdx.x == 0) {
        float v = 0.f;
        #pragma unroll
        for (int i = 0; i < NTHR / 32; i++) v += sh[i];
        g_partials[blockIdx.x] = v;
        __threadfence();
        unsigned t = atomicAdd(&g_ticket, 1u);
        s_last = (t == (unsigned)gridDim.x - 1u);
    }
    __syncthreads();
    if (!s_last) return;

    // ---- last block: deterministic double-precision finish ----
    const int tid = threadIdx.x;
    double v = 0.0;
    for (int i = tid; i < NBLK; i += NTHR)        // fixed-order per thread
        v += (double)g_partials[i];

    if (tid == 0) {
        for (int k = 8 * ngroups; k < NE; k++) {  // tail (empty when NE%8==0)
            float t0 = d[k], t1 = d[k + 1], u0 = y[k], u1 = y[k + 1];
            float a = gex_raw(u1 - u0) + gex_raw(t1 - t0)
                    - gex_raw(t1 - u0) - gex_raw(t0 - u1);
            v += 0.5 * (double)a - (double)gex_raw(t0 - u0);
        }
        v += 0.5 * ((double)gex_raw(d[0] - y[0]) - (double)gex_raw(d[NE] - y[NE]));
        v += (double)NE;
    }

    #pragma unroll
    for (int o = 16; o; o >>= 1) v += __shfl_down_sync(0xffffffffu, v, o);

    __shared__ double shd[NTHR / 32];
    if (lane == 0) shd[w] = v;
    __syncthreads();
    if (tid == 0) {
        double t = 0.0;
        #pragma unroll
        for (int i = 0; i < NTHR / 32; i++) t += shd[i];
        out[0] = (float)t;
        g_ticket = 0;                   // reset for next graph replay
    }
}

extern "C" void kernel_launch(void* const* d_in, const int* in_sizes, int n_in,
                              void* d_out, int out_size) {
    const float* d = (const float*)d_in[0];
    const float* y = (const float*)d_in[1];
    float* out = (float*)d_out;

    const int n  = in_sizes[0];
    const int NE = n - 2;               // 4,000,000 for N = 4,000,002
    const int ngroups = NE / 8;         // 8 consecutive k per group

    casa_fused<<<NBLK, NTHR>>>(d, y, NE, ngroups, out);
}